// round 12
// baseline (speedup 1.0000x reference)
#include <cuda_runtime.h>
#include <cuda_bf16.h>
#include <math.h>
#include <stdint.h>

#define NN      32768
#define KTOT    (3 * NN)
#define NPART   148
#define NTILES  (NN / 16)          // 2048 tiles of 16 nodes = 48 k-rows
#define EPSF    1e-5f
#define SSTR    56                 // gram smem row stride (48 k used)
#define ASTR    136                // chain A/G tile stride (128 k used)
#define BSTR    72                 // chain B tile stride (64 k-half used)

__device__ __constant__ float c_TPN = 0.022097086912079608f;  // 1/sqrt(16*128)
__device__ __constant__ float c_ISV = 0.08838834764831845f;   // 1/sqrt(128)

// ---------------- static device scratch ----------------
__device__ float g_part[NPART][128 * 128];
__device__ float g_G[128 * 128];
__device__ float g_Wc1[128 * 128];
__device__ float g_Wt[3][128 * 128];   // Wv[s] transposed (o-major)
__device__ float g_A[3][128 * 128];
__device__ float g_At[3][128 * 128];   // A_s transposed (o-major)
__device__ float g_fnp[8][128];        // per-CTA fn partials
__device__ __align__(16) float g_c[128];

// ---------------------------------------------------------------------------
__device__ __forceinline__ void mma_bf16(float* c, uint32_t a0, uint32_t a1,
                                         uint32_t a2, uint32_t a3,
                                         uint32_t b0, uint32_t b1) {
    asm("mma.sync.aligned.m16n8k16.row.col.f32.bf16.bf16.f32 "
        "{%0,%1,%2,%3}, {%4,%5,%6,%7}, {%8,%9}, {%0,%1,%2,%3};"
        : "+f"(c[0]), "+f"(c[1]), "+f"(c[2]), "+f"(c[3])
        : "r"(a0), "r"(a1), "r"(a2), "r"(a3), "r"(b0), "r"(b1));
}

__device__ __forceinline__ void bsplit2(float y0, float y1, uint32_t& ph,
                                        uint32_t& pl) {
    const __nv_bfloat16 h0 = __float2bfloat16(y0);
    const __nv_bfloat16 h1 = __float2bfloat16(y1);
    const __nv_bfloat16 l0 = __float2bfloat16(y0 - __bfloat162float(h0));
    const __nv_bfloat16 l1 = __float2bfloat16(y1 - __bfloat162float(h1));
    ph = ((uint32_t)__bfloat16_as_ushort(h1) << 16) | __bfloat16_as_ushort(h0);
    pl = ((uint32_t)__bfloat16_as_ushort(l1) << 16) | __bfloat16_as_ushort(l0);
}

// ---------------------------------------------------------------------------
// Prelaunch 1: transpose Wv into g_Wt.
// ---------------------------------------------------------------------------
__global__ void k_wt(const float* __restrict__ Wv) {
    const int s = blockIdx.x;
    const float* src = Wv + s * 16384;
#pragma unroll 4
    for (int i = 0; i < 64; i++) {
        const int e = threadIdx.x + 256 * i;
        const int v = e >> 7, o = e & 127;
        g_Wt[s][o * 128 + v] = __ldg(src + e);
    }
}

// Prelaunch 2: Wc1[v,o] = tpn * sum_u W_time[u] * W_tp1[u,v,o].
__global__ void k_wc1(const float* __restrict__ W_time,
                      const float* __restrict__ W_tp1) {
    const int e = blockIdx.x * blockDim.x + threadIdx.x;  // 0..16383
    float acc = 0.f;
#pragma unroll
    for (int u = 0; u < 16; u++)
        acc = fmaf(__ldg(W_time + u), __ldg(W_tp1 + u * 16384 + e), acc);
    g_Wc1[e] = acc * c_TPN;
}

// Prelaunch 3: no-op pad so k_gram is launch #4 (ncu's profiled slot).
__global__ void k_nop() {}

// ---------------------------------------------------------------------------
// Gram (EXACT R9 version — best measured): warp mma, hi/lo, upper-tri tiles.
// ---------------------------------------------------------------------------
__global__ void __launch_bounds__(256, 1)
k_gram(const float* __restrict__ feat, const float* __restrict__ times) {
    __shared__ __align__(16) __nv_bfloat16 sh[128][SSTR];
    __shared__ __align__(16) __nv_bfloat16 sl[128][SSTR];

    const int tid = threadIdx.x;
    const int w = tid >> 5, lane = tid & 31;
    const int gid = lane >> 2, tig = lane & 3;

    int rbl[9], jbl[9];
#pragma unroll
    for (int i = 0; i < 9; i++) {
        const int t = 9 * w + i;
        int rb = 0;
#pragma unroll
        for (int r = 1; r < 8; r++)
            if (t >= r * (17 - r)) rb = r;
        rbl[i] = rb;
        jbl[i] = 2 * rb + (t - rb * (17 - rb));
    }

    int rr_[6], qq_[6];
#pragma unroll
    for (int i = 0; i < 6; i++) {
        const int f = tid + 256 * i;
        rr_[i] = f / 96;
        qq_[i] = f - rr_[i] * 96;
    }

    float acc[9][4];
#pragma unroll
    for (int i = 0; i < 9; i++)
#pragma unroll
        for (int e = 0; e < 4; e++) acc[i][e] = 0.f;

    float4 pv[6];
    float ptm[6];
#pragma unroll
    for (int i = 0; i < 6; i++) {
        const int n = blockIdx.x * 16 + rr_[i];
        pv[i] = *(const float4*)(feat + (size_t)n * 512 + 128 + 4 * qq_[i]);
        ptm[i] = __ldg(times + n);
    }
#pragma unroll
    for (int i = 0; i < 6; i++) {
        const float comp[4] = {pv[i].x, pv[i].y, pv[i].z, pv[i].w};
        const int j = 4 * qq_[i];
#pragma unroll
        for (int e = 0; e < 4; e++) {
            const int jj = j + e;
            const int ch = jj / 3;
            const int kk = rr_[i] * 3 + (jj - 3 * ch);
            const float y = ptm[i] * comp[e];
            const __nv_bfloat16 h = __float2bfloat16(y);
            const __nv_bfloat16 l = __float2bfloat16(y - __bfloat162float(h));
            sh[ch][kk] = h;
            sl[ch][kk] = l;
        }
    }

    for (int tile = blockIdx.x; tile < NTILES; tile += NPART) {
        const int tn = tile + NPART;
        const bool more = (tn < NTILES);
        if (more) {
#pragma unroll
            for (int i = 0; i < 6; i++) {
                const int n = tn * 16 + rr_[i];
                pv[i] = *(const float4*)(feat + (size_t)n * 512 + 128 +
                                         4 * qq_[i]);
                ptm[i] = __ldg(times + n);
            }
        }
        __syncthreads();
#pragma unroll
        for (int ks = 0; ks < 3; ks++) {
            const int kb = 16 * ks + 2 * tig;
            uint32_t ah0 = 0, ah1 = 0, ah2 = 0, ah3 = 0;
            uint32_t al0 = 0, al1 = 0, al2 = 0, al3 = 0;
#pragma unroll
            for (int i = 0; i < 9; i++) {
                if (i == 0 || rbl[i] != rbl[i - 1]) {
                    const int ra = 16 * rbl[i] + gid;
                    ah0 = *(const uint32_t*)&sh[ra][kb];
                    ah1 = *(const uint32_t*)&sh[ra + 8][kb];
                    ah2 = *(const uint32_t*)&sh[ra][kb + 8];
                    ah3 = *(const uint32_t*)&sh[ra + 8][kb + 8];
                    al0 = *(const uint32_t*)&sl[ra][kb];
                    al1 = *(const uint32_t*)&sl[ra + 8][kb];
                    al2 = *(const uint32_t*)&sl[ra][kb + 8];
                    al3 = *(const uint32_t*)&sl[ra + 8][kb + 8];
                }
                const int rj = 8 * jbl[i] + gid;
                const uint32_t bh0 = *(const uint32_t*)&sh[rj][kb];
                const uint32_t bh1 = *(const uint32_t*)&sh[rj][kb + 8];
                const uint32_t bl0 = *(const uint32_t*)&sl[rj][kb];
                const uint32_t bl1 = *(const uint32_t*)&sl[rj][kb + 8];
                mma_bf16(acc[i], ah0, ah1, ah2, ah3, bh0, bh1);
                mma_bf16(acc[i], ah0, ah1, ah2, ah3, bl0, bl1);
                mma_bf16(acc[i], al0, al1, al2, al3, bh0, bh1);
            }
        }
        __syncthreads();
        if (more) {
#pragma unroll
            for (int i = 0; i < 6; i++) {
                const float comp[4] = {pv[i].x, pv[i].y, pv[i].z, pv[i].w};
                const int j = 4 * qq_[i];
#pragma unroll
                for (int e = 0; e < 4; e++) {
                    const int jj = j + e;
                    const int ch = jj / 3;
                    const int kk = rr_[i] * 3 + (jj - 3 * ch);
                    const float y = ptm[i] * comp[e];
                    const __nv_bfloat16 h = __float2bfloat16(y);
                    const __nv_bfloat16 l =
                        __float2bfloat16(y - __bfloat162float(h));
                    sh[ch][kk] = h;
                    sl[ch][kk] = l;
                }
            }
        }
    }

    float* outp = g_part[blockIdx.x];
#pragma unroll
    for (int i = 0; i < 9; i++) {
        const int row = 16 * rbl[i] + gid;
        const int col = 8 * jbl[i] + 2 * tig;
        *(float2*)(outp + row * 128 + col) = make_float2(acc[i][0], acc[i][1]);
        *(float2*)(outp + (row + 8) * 128 + col) =
            make_float2(acc[i][2], acc[i][3]);
    }
}

// Reduce partials with symmetric mirroring.
__global__ void k_greduce() {
    const int idx = blockIdx.x * blockDim.x + threadIdx.x;  // 0..16383
    const int ri = idx >> 7, cj = idx & 127;
    const int src = ((cj >> 3) >= 2 * (ri >> 4)) ? idx : (cj * 128 + ri);
    float s = 0.f;
#pragma unroll 4
    for (int p = 0; p < NPART; p++) s += g_part[p][src];
    g_G[idx] = s;
}

// ---------------------------------------------------------------------------
// Fused chain on tensor pipe (R9-validated; Wc1 hoisted to prelaunch).
// ---------------------------------------------------------------------------
__device__ __forceinline__ void cfence_sync() {
    __threadfence();
    asm volatile("barrier.cluster.arrive.aligned;" ::: "memory");
    asm volatile("barrier.cluster.wait.aligned;" ::: "memory");
}

__device__ __forceinline__ void conv_B_half(const float* __restrict__ src,
                                            int kh,
                                            __nv_bfloat16 (*Bh)[BSTR],
                                            __nv_bfloat16 (*Bl)[BSTR],
                                            int tid) {
#pragma unroll
    for (int i = 0; i < 8; i++) {
        const int e = tid + 256 * i;
        const int o = e >> 4;
        const int c4 = e & 15;
        const float4 v = *(const float4*)(src + o * 128 + 64 * kh + 4 * c4);
        uint32_t ph0, pl0, ph1, pl1;
        bsplit2(v.x, v.y, ph0, pl0);
        bsplit2(v.z, v.w, ph1, pl1);
        *(uint32_t*)&Bh[o][4 * c4] = ph0;
        *(uint32_t*)&Bh[o][4 * c4 + 2] = ph1;
        *(uint32_t*)&Bl[o][4 * c4] = pl0;
        *(uint32_t*)&Bl[o][4 * c4 + 2] = pl1;
    }
}

__device__ __forceinline__ void gemm_half(const __nv_bfloat16 (*Ah)[ASTR],
                                          const __nv_bfloat16 (*Al)[ASTR],
                                          const __nv_bfloat16 (*Bh)[BSTR],
                                          const __nv_bfloat16 (*Bl)[BSTR],
                                          int kh, int w, int gid, int tig,
                                          float acc[2][4]) {
#pragma unroll
    for (int ks = 0; ks < 4; ks++) {
        const int ka = 64 * kh + 16 * ks + 2 * tig;
        const int kb = 16 * ks + 2 * tig;
        const uint32_t ah0 = *(const uint32_t*)&Ah[gid][ka];
        const uint32_t ah1 = *(const uint32_t*)&Ah[gid + 8][ka];
        const uint32_t ah2 = *(const uint32_t*)&Ah[gid][ka + 8];
        const uint32_t ah3 = *(const uint32_t*)&Ah[gid + 8][ka + 8];
        const uint32_t al0 = *(const uint32_t*)&Al[gid][ka];
        const uint32_t al1 = *(const uint32_t*)&Al[gid + 8][ka];
        const uint32_t al2 = *(const uint32_t*)&Al[gid][ka + 8];
        const uint32_t al3 = *(const uint32_t*)&Al[gid + 8][ka + 8];
#pragma unroll
        for (int i = 0; i < 2; i++) {
            const int rj = 8 * (2 * w + i) + gid;
            const uint32_t bh0 = *(const uint32_t*)&Bh[rj][kb];
            const uint32_t bh1 = *(const uint32_t*)&Bh[rj][kb + 8];
            const uint32_t bl0 = *(const uint32_t*)&Bl[rj][kb];
            const uint32_t bl1 = *(const uint32_t*)&Bl[rj][kb + 8];
            mma_bf16(acc[i], ah0, ah1, ah2, ah3, bh0, bh1);
            mma_bf16(acc[i], ah0, ah1, ah2, ah3, bl0, bl1);
            mma_bf16(acc[i], al0, al1, al2, al3, bh0, bh1);
        }
    }
}

__global__ void __cluster_dims__(8, 1, 1) __launch_bounds__(256)
k_chain(const float* __restrict__ gamma_v, const float* __restrict__ W_r) {
    __shared__ __align__(16) __nv_bfloat16 sBh[128][BSTR];
    __shared__ __align__(16) __nv_bfloat16 sBl[128][BSTR];
    __shared__ __align__(16) __nv_bfloat16 sAh[16][ASTR];
    __shared__ __align__(16) __nv_bfloat16 sAl[16][ASTR];
    __shared__ float dvec[128];

    const int tid = threadIdx.x;
    const int w = tid >> 5, lane = tid & 31;
    const int gid = lane >> 2, tig = lane & 3;
    const int cta = blockIdx.x, r0 = cta * 16;

    const float* Aprev = g_Wc1;
    for (int s = 0; s < 3; s++) {
        // ---- build A tile: A' = Aprev(own rows) ⊙ d ----
#pragma unroll
        for (int i = 0; i < 2; i++) {
            const int e = tid + 256 * i;
            const int r = e >> 5, c4 = e & 31;
            float4 a = *(const float4*)(Aprev + (r0 + r) * 128 + 4 * c4);
            if (s > 0) {
                a.x *= dvec[4 * c4 + 0];
                a.y *= dvec[4 * c4 + 1];
                a.z *= dvec[4 * c4 + 2];
                a.w *= dvec[4 * c4 + 3];
            }
            uint32_t ph0, pl0, ph1, pl1;
            bsplit2(a.x, a.y, ph0, pl0);
            bsplit2(a.z, a.w, ph1, pl1);
            *(uint32_t*)&sAh[r][4 * c4] = ph0;
            *(uint32_t*)&sAh[r][4 * c4 + 2] = ph1;
            *(uint32_t*)&sAl[r][4 * c4] = pl0;
            *(uint32_t*)&sAl[r][4 * c4 + 2] = pl1;
        }

        // ---- GEMM1: A_s = A' @ Wv[s] * isv ----
        float a1[2][4];
#pragma unroll
        for (int i = 0; i < 2; i++)
#pragma unroll
            for (int e = 0; e < 4; e++) a1[i][e] = 0.f;
#pragma unroll
        for (int kh = 0; kh < 2; kh++) {
            __syncthreads();
            conv_B_half(g_Wt[s], kh, sBh, sBl, tid);
            __syncthreads();
            gemm_half(sAh, sAl, sBh, sBl, kh, w, gid, tig, a1);
        }

        float af[2][4];
#pragma unroll
        for (int i = 0; i < 2; i++) {
#pragma unroll
            for (int e = 0; e < 4; e++) af[i][e] = a1[i][e] * c_ISV;
            const int col = 8 * (2 * w + i) + 2 * tig;
            *(float2*)(g_A[s] + (r0 + gid) * 128 + col) =
                make_float2(af[i][0], af[i][1]);
            *(float2*)(g_A[s] + (r0 + gid + 8) * 128 + col) =
                make_float2(af[i][2], af[i][3]);
            g_At[s][col * 128 + r0 + gid] = af[i][0];
            g_At[s][(col + 1) * 128 + r0 + gid] = af[i][1];
            g_At[s][col * 128 + r0 + gid + 8] = af[i][2];
            g_At[s][(col + 1) * 128 + r0 + gid + 8] = af[i][3];
        }
        cfence_sync();

        // ---- rebuild A tile with G own rows ----
        __syncthreads();
#pragma unroll
        for (int i = 0; i < 2; i++) {
            const int e = tid + 256 * i;
            const int r = e >> 5, c4 = e & 31;
            const float4 v = *(const float4*)(g_G + (r0 + r) * 128 + 4 * c4);
            uint32_t ph0, pl0, ph1, pl1;
            bsplit2(v.x, v.y, ph0, pl0);
            bsplit2(v.z, v.w, ph1, pl1);
            *(uint32_t*)&sAh[r][4 * c4] = ph0;
            *(uint32_t*)&sAh[r][4 * c4 + 2] = ph1;
            *(uint32_t*)&sAl[r][4 * c4] = pl0;
            *(uint32_t*)&sAl[r][4 * c4 + 2] = pl1;
        }

        // ---- GEMM2: T = G @ A_s (fragments only) ----
        float tacc[2][4];
#pragma unroll
        for (int i = 0; i < 2; i++)
#pragma unroll
            for (int e = 0; e < 4; e++) tacc[i][e] = 0.f;
#pragma unroll
        for (int kh = 0; kh < 2; kh++) {
            __syncthreads();
            conv_B_half(g_At[s], kh, sBh, sBl, tid);
            __syncthreads();
            gemm_half(sAh, sAl, sBh, sBl, kh, w, gid, tig, tacc);
        }

        // ---- fn partials from matching fragments ----
        float q[4];
        q[0] = af[0][0] * tacc[0][0] + af[0][2] * tacc[0][2];
        q[1] = af[0][1] * tacc[0][1] + af[0][3] * tacc[0][3];
        q[2] = af[1][0] * tacc[1][0] + af[1][2] * tacc[1][2];
        q[3] = af[1][1] * tacc[1][1] + af[1][3] * tacc[1][3];
#pragma unroll
        for (int off = 4; off <= 16; off <<= 1) {
            q[0] += __shfl_xor_sync(0xffffffffu, q[0], off);
            q[1] += __shfl_xor_sync(0xffffffffu, q[1], off);
            q[2] += __shfl_xor_sync(0xffffffffu, q[2], off);
            q[3] += __shfl_xor_sync(0xffffffffu, q[3], off);
        }
        if (lane < 4) {
            g_fnp[cta][16 * w + 2 * lane + 0] = q[0];
            g_fnp[cta][16 * w + 2 * lane + 1] = q[1];
            g_fnp[cta][16 * w + 8 + 2 * lane + 0] = q[2];
            g_fnp[cta][16 * w + 8 + 2 * lane + 1] = q[3];
        }
        cfence_sync();

        if (tid < 128) {
            float sum = 0.f;
#pragma unroll
            for (int c = 0; c < 8; c++) sum += g_fnp[c][tid];
            dvec[tid] = __ldg(gamma_v + s * 128 + tid) *
                        rsqrtf(sum * (1.0f / (float)KTOT) + EPSF);
        }
        __syncthreads();
        Aprev = g_A[s];
    }

    if (tid < 16) {
        const int v = r0 + tid;
        float acc = 0.f;
#pragma unroll 8
        for (int o = 0; o < 128; o++)
            acc = fmaf(g_A[2][v * 128 + o], dvec[o] * __ldg(W_r + o), acc);
        g_c[v] = acc * c_ISV;
    }
}

// ---------------------------------------------------------------------------
// out[n,m] = time_n * sum_v x_v[n,v,m] * c[v]. Two nodes per warp.
// ---------------------------------------------------------------------------
__global__ void k_out(const float* __restrict__ feat,
                      const float* __restrict__ times,
                      float* __restrict__ out) {
    const int gw = (blockIdx.x * blockDim.x + threadIdx.x) >> 5;
    const int lane = threadIdx.x & 31;
    const int n0 = 2 * gw;
    if (n0 >= NN) return;

    const float* b0 = feat + (size_t)n0 * 512 + 128 + 12 * lane;
    const float4 x0 = *(const float4*)(b0);
    const float4 x1 = *(const float4*)(b0 + 4);
    const float4 x2 = *(const float4*)(b0 + 8);
    const float4 y0 = *(const float4*)(b0 + 512);
    const float4 y1 = *(const float4*)(b0 + 516);
    const float4 y2 = *(const float4*)(b0 + 520);
    const float4 cv = *(const float4*)(g_c + 4 * lane);

    float s0 = x0.x * cv.x + x0.w * cv.y + x1.z * cv.z + x2.y * cv.w;
    float s1 = x0.y * cv.x + x1.x * cv.y + x1.w * cv.z + x2.z * cv.w;
    float s2 = x0.z * cv.x + x1.y * cv.y + x2.x * cv.z + x2.w * cv.w;
    float t0 = y0.x * cv.x + y0.w * cv.y + y1.z * cv.z + y2.y * cv.w;
    float t1 = y0.y * cv.x + y1.x * cv.y + y1.w * cv.z + y2.z * cv.w;
    float t2 = y0.z * cv.x + y1.y * cv.y + y2.x * cv.z + y2.w * cv.w;

#pragma unroll
    for (int off = 16; off > 0; off >>= 1) {
        s0 += __shfl_xor_sync(0xffffffffu, s0, off);
        s1 += __shfl_xor_sync(0xffffffffu, s1, off);
        s2 += __shfl_xor_sync(0xffffffffu, s2, off);
        t0 += __shfl_xor_sync(0xffffffffu, t0, off);
        t1 += __shfl_xor_sync(0xffffffffu, t1, off);
        t2 += __shfl_xor_sync(0xffffffffu, t2, off);
    }
    if (lane == 0) {
        const float tm = times[n0];
        out[n0 * 3 + 0] = tm * s0;
        out[n0 * 3 + 1] = tm * s1;
        out[n0 * 3 + 2] = tm * s2;
    } else if (lane == 1) {
        const float tm = times[n0 + 1];
        out[n0 * 3 + 3] = tm * t0;
        out[n0 * 3 + 4] = tm * t1;
        out[n0 * 3 + 5] = tm * t2;
    }
}

// ---------------------------------------------------------------------------
extern "C" void kernel_launch(void* const* d_in, const int* in_sizes, int n_in,
                              void* d_out, int out_size) {
    const float* feat    = (const float*)d_in[0];
    const float* times   = (const float*)d_in[1];
    const float* W_time  = (const float*)d_in[2];
    const float* W_tp1   = (const float*)d_in[4];
    const float* Wv      = (const float*)d_in[6];
    const float* gamma_v = (const float*)d_in[9];
    const float* W_r     = (const float*)d_in[10];
    float* out = (float*)d_out;

    k_wt<<<3, 256>>>(Wv);                   // #1 (gram-independent prework)
    k_wc1<<<64, 256>>>(W_time, W_tp1);      // #2
    k_nop<<<1, 32>>>();                     // #3 (pad)
    k_gram<<<NPART, 256>>>(feat, times);    // #4  <- ncu profiled slot
    k_greduce<<<64, 256>>>();               // #5
    k_chain<<<8, 256>>>(gamma_v, W_r);      // #6
    k_out<<<(NN / 2 * 32) / 256, 256>>>(feat, times, out);  // #7
}

// round 13
// speedup vs baseline: 1.3404x; 1.3404x over previous
#include <cuda_runtime.h>
#include <cuda_bf16.h>
#include <math.h>
#include <stdint.h>

#define NN      32768
#define KTOT    (3 * NN)
#define NPART   148
#define NTILES  (NN / 16)          // 2048 tiles of 16 nodes = 48 k-rows
#define EPSF    1e-5f
#define SSTR    56                 // gram smem row stride (48 k used)
#define ASTR    136                // chain A/G tile stride (128 k used)
#define BSTR    72                 // chain B tile stride (64 k-half used)

__device__ __constant__ float c_TPN = 0.022097086912079608f;  // 1/sqrt(16*128)
__device__ __constant__ float c_ISV = 0.08838834764831845f;   // 1/sqrt(128)

// ---------------- static device scratch ----------------
__device__ float g_part[NPART][128 * 128];
__device__ float g_G[128 * 128];
__device__ float g_Wc1[128 * 128];
__device__ float g_Wt[3][128 * 128];   // Wv[s] transposed (o-major)
__device__ float g_A[3][128 * 128];
__device__ float g_At[3][128 * 128];   // A_s transposed (o-major)
__device__ float g_fnp[8][128];        // per-CTA fn partials
__device__ __align__(16) float g_c[128];

// ---------------------------------------------------------------------------
__device__ __forceinline__ void mma_bf16(float* c, uint32_t a0, uint32_t a1,
                                         uint32_t a2, uint32_t a3,
                                         uint32_t b0, uint32_t b1) {
    asm("mma.sync.aligned.m16n8k16.row.col.f32.bf16.bf16.f32 "
        "{%0,%1,%2,%3}, {%4,%5,%6,%7}, {%8,%9}, {%0,%1,%2,%3};"
        : "+f"(c[0]), "+f"(c[1]), "+f"(c[2]), "+f"(c[3])
        : "r"(a0), "r"(a1), "r"(a2), "r"(a3), "r"(b0), "r"(b1));
}

__device__ __forceinline__ void bsplit2(float y0, float y1, uint32_t& ph,
                                        uint32_t& pl) {
    const __nv_bfloat16 h0 = __float2bfloat16(y0);
    const __nv_bfloat16 h1 = __float2bfloat16(y1);
    const __nv_bfloat16 l0 = __float2bfloat16(y0 - __bfloat162float(h0));
    const __nv_bfloat16 l1 = __float2bfloat16(y1 - __bfloat162float(h1));
    ph = ((uint32_t)__bfloat16_as_ushort(h1) << 16) | __bfloat16_as_ushort(h0);
    pl = ((uint32_t)__bfloat16_as_ushort(l1) << 16) | __bfloat16_as_ushort(l0);
}

// ---------------------------------------------------------------------------
// Gram: SINGLE-term bf16 warp mma (lo-term dropped; error ~4e-6 in fn since
// rounding noise averages over 98304 rows). Halves the L1/LDS traffic that
// ncu R12 showed as the binding resource (75.6% L1, 23% tensor).
// ---------------------------------------------------------------------------
__global__ void __launch_bounds__(256)
k_gram(const float* __restrict__ feat, const float* __restrict__ times) {
    __shared__ __align__(16) __nv_bfloat16 sh[128][SSTR];  // 14336 B

    const int tid = threadIdx.x;
    const int w = tid >> 5, lane = tid & 31;
    const int gid = lane >> 2, tig = lane & 3;

    int rbl[9], jbl[9];
#pragma unroll
    for (int i = 0; i < 9; i++) {
        const int t = 9 * w + i;
        int rb = 0;
#pragma unroll
        for (int r = 1; r < 8; r++)
            if (t >= r * (17 - r)) rb = r;
        rbl[i] = rb;
        jbl[i] = 2 * rb + (t - rb * (17 - rb));
    }

    int rr_[6], qq_[6];
#pragma unroll
    for (int i = 0; i < 6; i++) {
        const int f = tid + 256 * i;
        rr_[i] = f / 96;
        qq_[i] = f - rr_[i] * 96;
    }

    float acc[9][4];
#pragma unroll
    for (int i = 0; i < 9; i++)
#pragma unroll
        for (int e = 0; e < 4; e++) acc[i][e] = 0.f;

    float4 pv[6];
    float ptm[6];
#pragma unroll
    for (int i = 0; i < 6; i++) {
        const int n = blockIdx.x * 16 + rr_[i];
        pv[i] = *(const float4*)(feat + (size_t)n * 512 + 128 + 4 * qq_[i]);
        ptm[i] = __ldg(times + n);
    }
#pragma unroll
    for (int i = 0; i < 6; i++) {
        const float comp[4] = {pv[i].x, pv[i].y, pv[i].z, pv[i].w};
        const int j = 4 * qq_[i];
#pragma unroll
        for (int e = 0; e < 4; e++) {
            const int jj = j + e;
            const int ch = jj / 3;
            const int kk = rr_[i] * 3 + (jj - 3 * ch);
            sh[ch][kk] = __float2bfloat16(ptm[i] * comp[e]);
        }
    }

    for (int tile = blockIdx.x; tile < NTILES; tile += NPART) {
        const int tn = tile + NPART;
        const bool more = (tn < NTILES);
        if (more) {  // prefetch next tile
#pragma unroll
            for (int i = 0; i < 6; i++) {
                const int n = tn * 16 + rr_[i];
                pv[i] = *(const float4*)(feat + (size_t)n * 512 + 128 +
                                         4 * qq_[i]);
                ptm[i] = __ldg(times + n);
            }
        }
        __syncthreads();  // buffer visible
#pragma unroll
        for (int ks = 0; ks < 3; ks++) {
            const int kb = 16 * ks + 2 * tig;
            uint32_t ah0 = 0, ah1 = 0, ah2 = 0, ah3 = 0;
#pragma unroll
            for (int i = 0; i < 9; i++) {
                if (i == 0 || rbl[i] != rbl[i - 1]) {
                    const int ra = 16 * rbl[i] + gid;
                    ah0 = *(const uint32_t*)&sh[ra][kb];
                    ah1 = *(const uint32_t*)&sh[ra + 8][kb];
                    ah2 = *(const uint32_t*)&sh[ra][kb + 8];
                    ah3 = *(const uint32_t*)&sh[ra + 8][kb + 8];
                }
                const int rj = 8 * jbl[i] + gid;
                const uint32_t bh0 = *(const uint32_t*)&sh[rj][kb];
                const uint32_t bh1 = *(const uint32_t*)&sh[rj][kb + 8];
                mma_bf16(acc[i], ah0, ah1, ah2, ah3, bh0, bh1);
            }
        }
        __syncthreads();  // reads done before overwrite
        if (more) {
#pragma unroll
            for (int i = 0; i < 6; i++) {
                const float comp[4] = {pv[i].x, pv[i].y, pv[i].z, pv[i].w};
                const int j = 4 * qq_[i];
#pragma unroll
                for (int e = 0; e < 4; e++) {
                    const int jj = j + e;
                    const int ch = jj / 3;
                    const int kk = rr_[i] * 3 + (jj - 3 * ch);
                    sh[ch][kk] = __float2bfloat16(ptm[i] * comp[e]);
                }
            }
        }
    }

    float* outp = g_part[blockIdx.x];
#pragma unroll
    for (int i = 0; i < 9; i++) {
        const int row = 16 * rbl[i] + gid;
        const int col = 8 * jbl[i] + 2 * tig;
        *(float2*)(outp + row * 128 + col) = make_float2(acc[i][0], acc[i][1]);
        *(float2*)(outp + (row + 8) * 128 + col) =
            make_float2(acc[i][2], acc[i][3]);
    }
}

// Reduce partials (mirrored) + transpose Wv into g_Wt (blocks 64..66).
__global__ void k_greduce(const float* __restrict__ Wv) {
    if (blockIdx.x >= 64) {
        const int s = blockIdx.x - 64;
        const float* src = Wv + s * 16384;
#pragma unroll 4
        for (int i = 0; i < 64; i++) {
            const int e = threadIdx.x + 256 * i;
            const int v = e >> 7, o = e & 127;
            g_Wt[s][o * 128 + v] = __ldg(src + e);
        }
        return;
    }
    const int idx = blockIdx.x * blockDim.x + threadIdx.x;  // 0..16383
    const int ri = idx >> 7, cj = idx & 127;
    const int src = ((cj >> 3) >= 2 * (ri >> 4)) ? idx : (cj * 128 + ri);
    float s = 0.f;
#pragma unroll 4
    for (int p = 0; p < NPART; p++) s += g_part[p][src];
    g_G[idx] = s;
}

// ---------------------------------------------------------------------------
// Fused chain on tensor pipe (EXACT R9/R11 version — validated at 97 µs).
// ---------------------------------------------------------------------------
__device__ __forceinline__ void cfence_sync() {
    __threadfence();
    asm volatile("barrier.cluster.arrive.aligned;" ::: "memory");
    asm volatile("barrier.cluster.wait.aligned;" ::: "memory");
}

__device__ __forceinline__ void conv_B_half(const float* __restrict__ src,
                                            int kh,
                                            __nv_bfloat16 (*Bh)[BSTR],
                                            __nv_bfloat16 (*Bl)[BSTR],
                                            int tid) {
#pragma unroll
    for (int i = 0; i < 8; i++) {
        const int e = tid + 256 * i;
        const int o = e >> 4;
        const int c4 = e & 15;
        const float4 v = *(const float4*)(src + o * 128 + 64 * kh + 4 * c4);
        uint32_t ph0, pl0, ph1, pl1;
        bsplit2(v.x, v.y, ph0, pl0);
        bsplit2(v.z, v.w, ph1, pl1);
        *(uint32_t*)&Bh[o][4 * c4] = ph0;
        *(uint32_t*)&Bh[o][4 * c4 + 2] = ph1;
        *(uint32_t*)&Bl[o][4 * c4] = pl0;
        *(uint32_t*)&Bl[o][4 * c4 + 2] = pl1;
    }
}

__device__ __forceinline__ void gemm_half(const __nv_bfloat16 (*Ah)[ASTR],
                                          const __nv_bfloat16 (*Al)[ASTR],
                                          const __nv_bfloat16 (*Bh)[BSTR],
                                          const __nv_bfloat16 (*Bl)[BSTR],
                                          int kh, int w, int gid, int tig,
                                          float acc[2][4]) {
#pragma unroll
    for (int ks = 0; ks < 4; ks++) {
        const int ka = 64 * kh + 16 * ks + 2 * tig;
        const int kb = 16 * ks + 2 * tig;
        const uint32_t ah0 = *(const uint32_t*)&Ah[gid][ka];
        const uint32_t ah1 = *(const uint32_t*)&Ah[gid + 8][ka];
        const uint32_t ah2 = *(const uint32_t*)&Ah[gid][ka + 8];
        const uint32_t ah3 = *(const uint32_t*)&Ah[gid + 8][ka + 8];
        const uint32_t al0 = *(const uint32_t*)&Al[gid][ka];
        const uint32_t al1 = *(const uint32_t*)&Al[gid + 8][ka];
        const uint32_t al2 = *(const uint32_t*)&Al[gid][ka + 8];
        const uint32_t al3 = *(const uint32_t*)&Al[gid + 8][ka + 8];
#pragma unroll
        for (int i = 0; i < 2; i++) {
            const int rj = 8 * (2 * w + i) + gid;
            const uint32_t bh0 = *(const uint32_t*)&Bh[rj][kb];
            const uint32_t bh1 = *(const uint32_t*)&Bh[rj][kb + 8];
            const uint32_t bl0 = *(const uint32_t*)&Bl[rj][kb];
            const uint32_t bl1 = *(const uint32_t*)&Bl[rj][kb + 8];
            mma_bf16(acc[i], ah0, ah1, ah2, ah3, bh0, bh1);
            mma_bf16(acc[i], ah0, ah1, ah2, ah3, bl0, bl1);
            mma_bf16(acc[i], al0, al1, al2, al3, bh0, bh1);
        }
    }
}

__global__ void __cluster_dims__(8, 1, 1) __launch_bounds__(256)
k_chain(const float* __restrict__ W_time, const float* __restrict__ W_tp1,
        const float* __restrict__ gamma_v, const float* __restrict__ W_r) {
    __shared__ __align__(16) __nv_bfloat16 sBh[128][BSTR];
    __shared__ __align__(16) __nv_bfloat16 sBl[128][BSTR];
    __shared__ __align__(16) __nv_bfloat16 sAh[16][ASTR];
    __shared__ __align__(16) __nv_bfloat16 sAl[16][ASTR];
    __shared__ float dvec[128];

    const int tid = threadIdx.x;
    const int w = tid >> 5, lane = tid & 31;
    const int gid = lane >> 2, tig = lane & 3;
    const int cta = blockIdx.x, r0 = cta * 16;

    // Wc1 own rows: Wc1[v,o] = tpn * sum_u wt[u]*Wtp1[u,v,o]
#pragma unroll
    for (int i = 0; i < 8; i++) {
        const int e = tid + 256 * i;
        const int v = r0 + (e >> 7);
        const int o = e & 127;
        float acc = 0.f;
#pragma unroll
        for (int u = 0; u < 16; u++)
            acc = fmaf(__ldg(W_time + u), __ldg(W_tp1 + u * 16384 + v * 128 + o),
                       acc);
        g_Wc1[v * 128 + o] = acc * c_TPN;
    }
    __syncthreads();

    const float* Aprev = g_Wc1;
    for (int s = 0; s < 3; s++) {
        // ---- build A tile: A' = Aprev(own rows) ⊙ d ----
#pragma unroll
        for (int i = 0; i < 2; i++) {
            const int e = tid + 256 * i;
            const int r = e >> 5, c4 = e & 31;
            float4 a = *(const float4*)(Aprev + (r0 + r) * 128 + 4 * c4);
            if (s > 0) {
                a.x *= dvec[4 * c4 + 0];
                a.y *= dvec[4 * c4 + 1];
                a.z *= dvec[4 * c4 + 2];
                a.w *= dvec[4 * c4 + 3];
            }
            uint32_t ph0, pl0, ph1, pl1;
            bsplit2(a.x, a.y, ph0, pl0);
            bsplit2(a.z, a.w, ph1, pl1);
            *(uint32_t*)&sAh[r][4 * c4] = ph0;
            *(uint32_t*)&sAh[r][4 * c4 + 2] = ph1;
            *(uint32_t*)&sAl[r][4 * c4] = pl0;
            *(uint32_t*)&sAl[r][4 * c4 + 2] = pl1;
        }

        // ---- GEMM1: A_s = A' @ Wv[s] * isv ----
        float a1[2][4];
#pragma unroll
        for (int i = 0; i < 2; i++)
#pragma unroll
            for (int e = 0; e < 4; e++) a1[i][e] = 0.f;
#pragma unroll
        for (int kh = 0; kh < 2; kh++) {
            __syncthreads();
            conv_B_half(g_Wt[s], kh, sBh, sBl, tid);
            __syncthreads();
            gemm_half(sAh, sAl, sBh, sBl, kh, w, gid, tig, a1);
        }

        float af[2][4];
#pragma unroll
        for (int i = 0; i < 2; i++) {
#pragma unroll
            for (int e = 0; e < 4; e++) af[i][e] = a1[i][e] * c_ISV;
            const int col = 8 * (2 * w + i) + 2 * tig;
            *(float2*)(g_A[s] + (r0 + gid) * 128 + col) =
                make_float2(af[i][0], af[i][1]);
            *(float2*)(g_A[s] + (r0 + gid + 8) * 128 + col) =
                make_float2(af[i][2], af[i][3]);
            g_At[s][col * 128 + r0 + gid] = af[i][0];
            g_At[s][(col + 1) * 128 + r0 + gid] = af[i][1];
            g_At[s][col * 128 + r0 + gid + 8] = af[i][2];
            g_At[s][(col + 1) * 128 + r0 + gid + 8] = af[i][3];
        }
        cfence_sync();

        // ---- rebuild A tile with G own rows ----
        __syncthreads();
#pragma unroll
        for (int i = 0; i < 2; i++) {
            const int e = tid + 256 * i;
            const int r = e >> 5, c4 = e & 31;
            const float4 v = *(const float4*)(g_G + (r0 + r) * 128 + 4 * c4);
            uint32_t ph0, pl0, ph1, pl1;
            bsplit2(v.x, v.y, ph0, pl0);
            bsplit2(v.z, v.w, ph1, pl1);
            *(uint32_t*)&sAh[r][4 * c4] = ph0;
            *(uint32_t*)&sAh[r][4 * c4 + 2] = ph1;
            *(uint32_t*)&sAl[r][4 * c4] = pl0;
            *(uint32_t*)&sAl[r][4 * c4 + 2] = pl1;
        }

        // ---- GEMM2: T = G @ A_s (fragments only) ----
        float tacc[2][4];
#pragma unroll
        for (int i = 0; i < 2; i++)
#pragma unroll
            for (int e = 0; e < 4; e++) tacc[i][e] = 0.f;
#pragma unroll
        for (int kh = 0; kh < 2; kh++) {
            __syncthreads();
            conv_B_half(g_At[s], kh, sBh, sBl, tid);
            __syncthreads();
            gemm_half(sAh, sAl, sBh, sBl, kh, w, gid, tig, tacc);
        }

        // ---- fn partials from matching fragments ----
        float q[4];
        q[0] = af[0][0] * tacc[0][0] + af[0][2] * tacc[0][2];
        q[1] = af[0][1] * tacc[0][1] + af[0][3] * tacc[0][3];
        q[2] = af[1][0] * tacc[1][0] + af[1][2] * tacc[1][2];
        q[3] = af[1][1] * tacc[1][1] + af[1][3] * tacc[1][3];
#pragma unroll
        for (int off = 4; off <= 16; off <<= 1) {
            q[0] += __shfl_xor_sync(0xffffffffu, q[0], off);
            q[1] += __shfl_xor_sync(0xffffffffu, q[1], off);
            q[2] += __shfl_xor_sync(0xffffffffu, q[2], off);
            q[3] += __shfl_xor_sync(0xffffffffu, q[3], off);
        }
        if (lane < 4) {
            g_fnp[cta][16 * w + 2 * lane + 0] = q[0];
            g_fnp[cta][16 * w + 2 * lane + 1] = q[1];
            g_fnp[cta][16 * w + 8 + 2 * lane + 0] = q[2];
            g_fnp[cta][16 * w + 8 + 2 * lane + 1] = q[3];
        }
        cfence_sync();

        if (tid < 128) {
            float sum = 0.f;
#pragma unroll
            for (int c = 0; c < 8; c++) sum += g_fnp[c][tid];
            dvec[tid] = __ldg(gamma_v + s * 128 + tid) *
                        rsqrtf(sum * (1.0f / (float)KTOT) + EPSF);
        }
        __syncthreads();
        Aprev = g_A[s];
    }

    if (tid < 16) {
        const int v = r0 + tid;
        float acc = 0.f;
#pragma unroll 8
        for (int o = 0; o < 128; o++)
            acc = fmaf(g_A[2][v * 128 + o], dvec[o] * __ldg(W_r + o), acc);
        g_c[v] = acc * c_ISV;
    }
}

// ---------------------------------------------------------------------------
// out[n,m] = time_n * sum_v x_v[n,v,m] * c[v]. Two nodes per warp.
// ---------------------------------------------------------------------------
__global__ void k_out(const float* __restrict__ feat,
                      const float* __restrict__ times,
                      float* __restrict__ out) {
    const int gw = (blockIdx.x * blockDim.x + threadIdx.x) >> 5;
    const int lane = threadIdx.x & 31;
    const int n0 = 2 * gw;
    if (n0 >= NN) return;

    const float* b0 = feat + (size_t)n0 * 512 + 128 + 12 * lane;
    const float4 x0 = *(const float4*)(b0);
    const float4 x1 = *(const float4*)(b0 + 4);
    const float4 x2 = *(const float4*)(b0 + 8);
    const float4 y0 = *(const float4*)(b0 + 512);
    const float4 y1 = *(const float4*)(b0 + 516);
    const float4 y2 = *(const float4*)(b0 + 520);
    const float4 cv = *(const float4*)(g_c + 4 * lane);

    float s0 = x0.x * cv.x + x0.w * cv.y + x1.z * cv.z + x2.y * cv.w;
    float s1 = x0.y * cv.x + x1.x * cv.y + x1.w * cv.z + x2.z * cv.w;
    float s2 = x0.z * cv.x + x1.y * cv.y + x2.x * cv.z + x2.w * cv.w;
    float t0 = y0.x * cv.x + y0.w * cv.y + y1.z * cv.z + y2.y * cv.w;
    float t1 = y0.y * cv.x + y1.x * cv.y + y1.w * cv.z + y2.z * cv.w;
    float t2 = y0.z * cv.x + y1.y * cv.y + y2.x * cv.z + y2.w * cv.w;

#pragma unroll
    for (int off = 16; off > 0; off >>= 1) {
        s0 += __shfl_xor_sync(0xffffffffu, s0, off);
        s1 += __shfl_xor_sync(0xffffffffu, s1, off);
        s2 += __shfl_xor_sync(0xffffffffu, s2, off);
        t0 += __shfl_xor_sync(0xffffffffu, t0, off);
        t1 += __shfl_xor_sync(0xffffffffu, t1, off);
        t2 += __shfl_xor_sync(0xffffffffu, t2, off);
    }
    if (lane == 0) {
        const float tm = times[n0];
        out[n0 * 3 + 0] = tm * s0;
        out[n0 * 3 + 1] = tm * s1;
        out[n0 * 3 + 2] = tm * s2;
    } else if (lane == 1) {
        const float tm = times[n0 + 1];
        out[n0 * 3 + 3] = tm * t0;
        out[n0 * 3 + 4] = tm * t1;
        out[n0 * 3 + 5] = tm * t2;
    }
}

// ---------------------------------------------------------------------------
extern "C" void kernel_launch(void* const* d_in, const int* in_sizes, int n_in,
                              void* d_out, int out_size) {
    const float* feat    = (const float*)d_in[0];
    const float* times   = (const float*)d_in[1];
    const float* W_time  = (const float*)d_in[2];
    const float* W_tp1   = (const float*)d_in[4];
    const float* Wv      = (const float*)d_in[6];
    const float* gamma_v = (const float*)d_in[9];
    const float* W_r     = (const float*)d_in[10];
    float* out = (float*)d_out;

    k_gram<<<NPART, 256>>>(feat, times);
    k_greduce<<<67, 256>>>(Wv);
    k_chain<<<8, 256>>>(W_time, W_tp1, gamma_v, W_r);
    k_out<<<(NN / 2 * 32) / 256, 256>>>(feat, times, out);
}

// round 14
// speedup vs baseline: 1.4144x; 1.0552x over previous
#include <cuda_runtime.h>
#include <cuda_bf16.h>
#include <math.h>
#include <stdint.h>

#define NN      32768
#define KTOT    (3 * NN)
#define NPART   148
#define NTILES  (NN / 16)          // 2048 tiles of 16 nodes = 48 k-rows
#define EPSF    1e-5f
#define SSTR    56                 // gram smem row stride (48 k used)
#define ASTR    136                // chain A/G tile stride (128 k used)
#define BSTR    72                 // chain B tile stride (64 k-half used)

__device__ __constant__ float c_TPN = 0.022097086912079608f;  // 1/sqrt(16*128)
__device__ __constant__ float c_ISV = 0.08838834764831845f;   // 1/sqrt(128)

// ---------------- static device scratch ----------------
__device__ float g_part[NPART][128 * 128];
__device__ float g_G[128 * 128];
__device__ float g_Wc1[128 * 128];
__device__ uint4 g_Wtbh[3 * 2048];     // Wv^T prepacked bf16 hi (tile layout)
__device__ uint4 g_Wtbl[3 * 2048];     // Wv^T prepacked bf16 lo
__device__ float g_A[3][128 * 128];
__device__ float g_At[3][128 * 128];   // A_s transposed (o-major)
__device__ float g_fnp[8][128];        // per-CTA fn partials
__device__ __align__(16) float g_c[128];

// ---------------------------------------------------------------------------
__device__ __forceinline__ void mma_bf16(float* c, uint32_t a0, uint32_t a1,
                                         uint32_t a2, uint32_t a3,
                                         uint32_t b0, uint32_t b1) {
    asm("mma.sync.aligned.m16n8k16.row.col.f32.bf16.bf16.f32 "
        "{%0,%1,%2,%3}, {%4,%5,%6,%7}, {%8,%9}, {%0,%1,%2,%3};"
        : "+f"(c[0]), "+f"(c[1]), "+f"(c[2]), "+f"(c[3])
        : "r"(a0), "r"(a1), "r"(a2), "r"(a3), "r"(b0), "r"(b1));
}

__device__ __forceinline__ void bsplit2(float y0, float y1, uint32_t& ph,
                                        uint32_t& pl) {
    const __nv_bfloat16 h0 = __float2bfloat16(y0);
    const __nv_bfloat16 h1 = __float2bfloat16(y1);
    const __nv_bfloat16 l0 = __float2bfloat16(y0 - __bfloat162float(h0));
    const __nv_bfloat16 l1 = __float2bfloat16(y1 - __bfloat162float(h1));
    ph = ((uint32_t)__bfloat16_as_ushort(h1) << 16) | __bfloat16_as_ushort(h0);
    pl = ((uint32_t)__bfloat16_as_ushort(l1) << 16) | __bfloat16_as_ushort(l0);
}

// ---------------------------------------------------------------------------
// Gram (EXACT R13 version — validated at 82.6 µs): single-term bf16 warp mma.
// ---------------------------------------------------------------------------
__global__ void __launch_bounds__(256)
k_gram(const float* __restrict__ feat, const float* __restrict__ times) {
    __shared__ __align__(16) __nv_bfloat16 sh[128][SSTR];  // 14336 B

    const int tid = threadIdx.x;
    const int w = tid >> 5, lane = tid & 31;
    const int gid = lane >> 2, tig = lane & 3;

    int rbl[9], jbl[9];
#pragma unroll
    for (int i = 0; i < 9; i++) {
        const int t = 9 * w + i;
        int rb = 0;
#pragma unroll
        for (int r = 1; r < 8; r++)
            if (t >= r * (17 - r)) rb = r;
        rbl[i] = rb;
        jbl[i] = 2 * rb + (t - rb * (17 - rb));
    }

    int rr_[6], qq_[6];
#pragma unroll
    for (int i = 0; i < 6; i++) {
        const int f = tid + 256 * i;
        rr_[i] = f / 96;
        qq_[i] = f - rr_[i] * 96;
    }

    float acc[9][4];
#pragma unroll
    for (int i = 0; i < 9; i++)
#pragma unroll
        for (int e = 0; e < 4; e++) acc[i][e] = 0.f;

    float4 pv[6];
    float ptm[6];
#pragma unroll
    for (int i = 0; i < 6; i++) {
        const int n = blockIdx.x * 16 + rr_[i];
        pv[i] = *(const float4*)(feat + (size_t)n * 512 + 128 + 4 * qq_[i]);
        ptm[i] = __ldg(times + n);
    }
#pragma unroll
    for (int i = 0; i < 6; i++) {
        const float comp[4] = {pv[i].x, pv[i].y, pv[i].z, pv[i].w};
        const int j = 4 * qq_[i];
#pragma unroll
        for (int e = 0; e < 4; e++) {
            const int jj = j + e;
            const int ch = jj / 3;
            const int kk = rr_[i] * 3 + (jj - 3 * ch);
            sh[ch][kk] = __float2bfloat16(ptm[i] * comp[e]);
        }
    }

    for (int tile = blockIdx.x; tile < NTILES; tile += NPART) {
        const int tn = tile + NPART;
        const bool more = (tn < NTILES);
        if (more) {
#pragma unroll
            for (int i = 0; i < 6; i++) {
                const int n = tn * 16 + rr_[i];
                pv[i] = *(const float4*)(feat + (size_t)n * 512 + 128 +
                                         4 * qq_[i]);
                ptm[i] = __ldg(times + n);
            }
        }
        __syncthreads();
#pragma unroll
        for (int ks = 0; ks < 3; ks++) {
            const int kb = 16 * ks + 2 * tig;
            uint32_t ah0 = 0, ah1 = 0, ah2 = 0, ah3 = 0;
#pragma unroll
            for (int i = 0; i < 9; i++) {
                if (i == 0 || rbl[i] != rbl[i - 1]) {
                    const int ra = 16 * rbl[i] + gid;
                    ah0 = *(const uint32_t*)&sh[ra][kb];
                    ah1 = *(const uint32_t*)&sh[ra + 8][kb];
                    ah2 = *(const uint32_t*)&sh[ra][kb + 8];
                    ah3 = *(const uint32_t*)&sh[ra + 8][kb + 8];
                }
                const int rj = 8 * jbl[i] + gid;
                const uint32_t bh0 = *(const uint32_t*)&sh[rj][kb];
                const uint32_t bh1 = *(const uint32_t*)&sh[rj][kb + 8];
                mma_bf16(acc[i], ah0, ah1, ah2, ah3, bh0, bh1);
            }
        }
        __syncthreads();
        if (more) {
#pragma unroll
            for (int i = 0; i < 6; i++) {
                const float comp[4] = {pv[i].x, pv[i].y, pv[i].z, pv[i].w};
                const int j = 4 * qq_[i];
#pragma unroll
                for (int e = 0; e < 4; e++) {
                    const int jj = j + e;
                    const int ch = jj / 3;
                    const int kk = rr_[i] * 3 + (jj - 3 * ch);
                    sh[ch][kk] = __float2bfloat16(ptm[i] * comp[e]);
                }
            }
        }
    }

    float* outp = g_part[blockIdx.x];
#pragma unroll
    for (int i = 0; i < 9; i++) {
        const int row = 16 * rbl[i] + gid;
        const int col = 8 * jbl[i] + 2 * tig;
        *(float2*)(outp + row * 128 + col) = make_float2(acc[i][0], acc[i][1]);
        *(float2*)(outp + (row + 8) * 128 + col) =
            make_float2(acc[i][2], acc[i][3]);
    }
}

// Reduce partials (mirrored) + prepack Wv^T as bf16 hi/lo (blocks 64..66).
// Packed layout matches the chain's smem tile fill exactly:
//   slot idx in [0,2048): kh=idx>>10, o=(idx&1023)>>3, c8=idx&7
//   covers Wt[o][kh*64 + 8*c8 .. +8) = Wv[v][o] for 8 consecutive v.
__global__ void k_greduce(const float* __restrict__ Wv) {
    if (blockIdx.x >= 64) {
        const int s = blockIdx.x - 64;
        const float* src = Wv + s * 16384;
#pragma unroll
        for (int it = 0; it < 8; it++) {
            const int idx = threadIdx.x + 256 * it;  // 0..2047
            const int kh = idx >> 10;
            const int slot = idx & 1023;
            const int o = slot >> 3, c8 = slot & 7;
            const int v0 = kh * 64 + 8 * c8;
            float y[8];
#pragma unroll
            for (int j = 0; j < 8; j++) y[j] = __ldg(src + (v0 + j) * 128 + o);
            uint32_t h[4], l[4];
#pragma unroll
            for (int j = 0; j < 4; j++)
                bsplit2(y[2 * j], y[2 * j + 1], h[j], l[j]);
            g_Wtbh[s * 2048 + idx] = make_uint4(h[0], h[1], h[2], h[3]);
            g_Wtbl[s * 2048 + idx] = make_uint4(l[0], l[1], l[2], l[3]);
        }
        return;
    }
    const int idx = blockIdx.x * blockDim.x + threadIdx.x;  // 0..16383
    const int ri = idx >> 7, cj = idx & 127;
    const int src = ((cj >> 3) >= 2 * (ri >> 4)) ? idx : (cj * 128 + ri);
    float s = 0.f;
#pragma unroll 4
    for (int p = 0; p < NPART; p++) s += g_part[p][src];
    g_G[idx] = s;
}

// ---------------------------------------------------------------------------
// Fused chain on tensor pipe. GEMM1's B tiles are now straight copies of the
// prepacked Wt (no conversion); GEMM2's At tiles still convert in-kernel.
// ---------------------------------------------------------------------------
__device__ __forceinline__ void cfence_sync() {
    __threadfence();
    asm volatile("barrier.cluster.arrive.aligned;" ::: "memory");
    asm volatile("barrier.cluster.wait.aligned;" ::: "memory");
}

__device__ __forceinline__ void copy_B_half(const uint4* __restrict__ srch,
                                            const uint4* __restrict__ srcl,
                                            __nv_bfloat16 (*Bh)[BSTR],
                                            __nv_bfloat16 (*Bl)[BSTR],
                                            int tid) {
#pragma unroll
    for (int i = 0; i < 4; i++) {
        const int e = tid + 256 * i;   // 0..1023 uint4 slots
        const int o = e >> 3, c8 = e & 7;
        *(uint4*)&Bh[o][8 * c8] = srch[e];
        *(uint4*)&Bl[o][8 * c8] = srcl[e];
    }
}

__device__ __forceinline__ void conv_B_half(const float* __restrict__ src,
                                            int kh,
                                            __nv_bfloat16 (*Bh)[BSTR],
                                            __nv_bfloat16 (*Bl)[BSTR],
                                            int tid) {
#pragma unroll
    for (int i = 0; i < 8; i++) {
        const int e = tid + 256 * i;
        const int o = e >> 4;
        const int c4 = e & 15;
        const float4 v = *(const float4*)(src + o * 128 + 64 * kh + 4 * c4);
        uint32_t ph0, pl0, ph1, pl1;
        bsplit2(v.x, v.y, ph0, pl0);
        bsplit2(v.z, v.w, ph1, pl1);
        *(uint32_t*)&Bh[o][4 * c4] = ph0;
        *(uint32_t*)&Bh[o][4 * c4 + 2] = ph1;
        *(uint32_t*)&Bl[o][4 * c4] = pl0;
        *(uint32_t*)&Bl[o][4 * c4 + 2] = pl1;
    }
}

__device__ __forceinline__ void gemm_half(const __nv_bfloat16 (*Ah)[ASTR],
                                          const __nv_bfloat16 (*Al)[ASTR],
                                          const __nv_bfloat16 (*Bh)[BSTR],
                                          const __nv_bfloat16 (*Bl)[BSTR],
                                          int kh, int w, int gid, int tig,
                                          float acc[2][4]) {
#pragma unroll
    for (int ks = 0; ks < 4; ks++) {
        const int ka = 64 * kh + 16 * ks + 2 * tig;
        const int kb = 16 * ks + 2 * tig;
        const uint32_t ah0 = *(const uint32_t*)&Ah[gid][ka];
        const uint32_t ah1 = *(const uint32_t*)&Ah[gid + 8][ka];
        const uint32_t ah2 = *(const uint32_t*)&Ah[gid][ka + 8];
        const uint32_t ah3 = *(const uint32_t*)&Ah[gid + 8][ka + 8];
        const uint32_t al0 = *(const uint32_t*)&Al[gid][ka];
        const uint32_t al1 = *(const uint32_t*)&Al[gid + 8][ka];
        const uint32_t al2 = *(const uint32_t*)&Al[gid][ka + 8];
        const uint32_t al3 = *(const uint32_t*)&Al[gid + 8][ka + 8];
#pragma unroll
        for (int i = 0; i < 2; i++) {
            const int rj = 8 * (2 * w + i) + gid;
            const uint32_t bh0 = *(const uint32_t*)&Bh[rj][kb];
            const uint32_t bh1 = *(const uint32_t*)&Bh[rj][kb + 8];
            const uint32_t bl0 = *(const uint32_t*)&Bl[rj][kb];
            const uint32_t bl1 = *(const uint32_t*)&Bl[rj][kb + 8];
            mma_bf16(acc[i], ah0, ah1, ah2, ah3, bh0, bh1);
            mma_bf16(acc[i], ah0, ah1, ah2, ah3, bl0, bl1);
            mma_bf16(acc[i], al0, al1, al2, al3, bh0, bh1);
        }
    }
}

__global__ void __cluster_dims__(8, 1, 1) __launch_bounds__(256)
k_chain(const float* __restrict__ W_time, const float* __restrict__ W_tp1,
        const float* __restrict__ gamma_v, const float* __restrict__ W_r) {
    __shared__ __align__(16) __nv_bfloat16 sBh[128][BSTR];
    __shared__ __align__(16) __nv_bfloat16 sBl[128][BSTR];
    __shared__ __align__(16) __nv_bfloat16 sAh[16][ASTR];
    __shared__ __align__(16) __nv_bfloat16 sAl[16][ASTR];
    __shared__ float dvec[128];

    const int tid = threadIdx.x;
    const int w = tid >> 5, lane = tid & 31;
    const int gid = lane >> 2, tig = lane & 3;
    const int cta = blockIdx.x, r0 = cta * 16;

    // Wc1 own rows: Wc1[v,o] = tpn * sum_u wt[u]*Wtp1[u,v,o]  (kept in g_A[2]
    // scratch? no — dedicated buffer g_Wc1 removed; reuse g_At[2] is unsafe.
    // Use local global buffer below.)
    // Note: g_Wc1 renamed usage — store into g_A? Keep separate: use g_At[2]
    // is used later. Use dedicated array:
#pragma unroll
    for (int i = 0; i < 8; i++) {
        const int e = tid + 256 * i;
        const int v = r0 + (e >> 7);
        const int o = e & 127;
        float acc = 0.f;
#pragma unroll
        for (int u = 0; u < 16; u++)
            acc = fmaf(__ldg(W_time + u), __ldg(W_tp1 + u * 16384 + v * 128 + o),
                       acc);
        g_Wc1[v * 128 + o] = acc * c_TPN;
    }
    __syncthreads();

    const float* Aprev = g_Wc1;
    for (int s = 0; s < 3; s++) {
        // ---- build A tile: A' = Aprev(own rows) ⊙ d ----
#pragma unroll
        for (int i = 0; i < 2; i++) {
            const int e = tid + 256 * i;
            const int r = e >> 5, c4 = e & 31;
            float4 a = *(const float4*)(Aprev + (r0 + r) * 128 + 4 * c4);
            if (s > 0) {
                a.x *= dvec[4 * c4 + 0];
                a.y *= dvec[4 * c4 + 1];
                a.z *= dvec[4 * c4 + 2];
                a.w *= dvec[4 * c4 + 3];
            }
            uint32_t ph0, pl0, ph1, pl1;
            bsplit2(a.x, a.y, ph0, pl0);
            bsplit2(a.z, a.w, ph1, pl1);
            *(uint32_t*)&sAh[r][4 * c4] = ph0;
            *(uint32_t*)&sAh[r][4 * c4 + 2] = ph1;
            *(uint32_t*)&sAl[r][4 * c4] = pl0;
            *(uint32_t*)&sAl[r][4 * c4 + 2] = pl1;
        }

        // ---- GEMM1: A_s = A' @ Wv[s] * isv  (B tiles: prepacked copies) ----
        float a1[2][4];
#pragma unroll
        for (int i = 0; i < 2; i++)
#pragma unroll
            for (int e = 0; e < 4; e++) a1[i][e] = 0.f;
#pragma unroll
        for (int kh = 0; kh < 2; kh++) {
            __syncthreads();
            copy_B_half(g_Wtbh + (s * 2 + kh) * 1024,
                        g_Wtbl + (s * 2 + kh) * 1024, sBh, sBl, tid);
            __syncthreads();
            gemm_half(sAh, sAl, sBh, sBl, kh, w, gid, tig, a1);
        }

        float af[2][4];
#pragma unroll
        for (int i = 0; i < 2; i++) {
#pragma unroll
            for (int e = 0; e < 4; e++) af[i][e] = a1[i][e] * c_ISV;
            const int col = 8 * (2 * w + i) + 2 * tig;
            *(float2*)(g_A[s] + (r0 + gid) * 128 + col) =
                make_float2(af[i][0], af[i][1]);
            *(float2*)(g_A[s] + (r0 + gid + 8) * 128 + col) =
                make_float2(af[i][2], af[i][3]);
            g_At[s][col * 128 + r0 + gid] = af[i][0];
            g_At[s][(col + 1) * 128 + r0 + gid] = af[i][1];
            g_At[s][col * 128 + r0 + gid + 8] = af[i][2];
            g_At[s][(col + 1) * 128 + r0 + gid + 8] = af[i][3];
        }
        cfence_sync();

        // ---- rebuild A tile with G own rows ----
        __syncthreads();
#pragma unroll
        for (int i = 0; i < 2; i++) {
            const int e = tid + 256 * i;
            const int r = e >> 5, c4 = e & 31;
            const float4 v = *(const float4*)(g_G + (r0 + r) * 128 + 4 * c4);
            uint32_t ph0, pl0, ph1, pl1;
            bsplit2(v.x, v.y, ph0, pl0);
            bsplit2(v.z, v.w, ph1, pl1);
            *(uint32_t*)&sAh[r][4 * c4] = ph0;
            *(uint32_t*)&sAh[r][4 * c4 + 2] = ph1;
            *(uint32_t*)&sAl[r][4 * c4] = pl0;
            *(uint32_t*)&sAl[r][4 * c4 + 2] = pl1;
        }

        // ---- GEMM2: T = G @ A_s (fragments only) ----
        float tacc[2][4];
#pragma unroll
        for (int i = 0; i < 2; i++)
#pragma unroll
            for (int e = 0; e < 4; e++) tacc[i][e] = 0.f;
#pragma unroll
        for (int kh = 0; kh < 2; kh++) {
            __syncthreads();
            conv_B_half(g_At[s], kh, sBh, sBl, tid);
            __syncthreads();
            gemm_half(sAh, sAl, sBh, sBl, kh, w, gid, tig, tacc);
        }

        // ---- fn partials from matching fragments ----
        float q[4];
        q[0] = af[0][0] * tacc[0][0] + af[0][2] * tacc[0][2];
        q[1] = af[0][1] * tacc[0][1] + af[0][3] * tacc[0][3];
        q[2] = af[1][0] * tacc[1][0] + af[1][2] * tacc[1][2];
        q[3] = af[1][1] * tacc[1][1] + af[1][3] * tacc[1][3];
#pragma unroll
        for (int off = 4; off <= 16; off <<= 1) {
            q[0] += __shfl_xor_sync(0xffffffffu, q[0], off);
            q[1] += __shfl_xor_sync(0xffffffffu, q[1], off);
            q[2] += __shfl_xor_sync(0xffffffffu, q[2], off);
            q[3] += __shfl_xor_sync(0xffffffffu, q[3], off);
        }
        if (lane < 4) {
            g_fnp[cta][16 * w + 2 * lane + 0] = q[0];
            g_fnp[cta][16 * w + 2 * lane + 1] = q[1];
            g_fnp[cta][16 * w + 8 + 2 * lane + 0] = q[2];
            g_fnp[cta][16 * w + 8 + 2 * lane + 1] = q[3];
        }
        cfence_sync();

        if (tid < 128) {
            float sum = 0.f;
#pragma unroll
            for (int c = 0; c < 8; c++) sum += g_fnp[c][tid];
            dvec[tid] = __ldg(gamma_v + s * 128 + tid) *
                        rsqrtf(sum * (1.0f / (float)KTOT) + EPSF);
        }
        __syncthreads();
        Aprev = g_A[s];
    }

    if (tid < 16) {
        const int v = r0 + tid;
        float acc = 0.f;
#pragma unroll 8
        for (int o = 0; o < 128; o++)
            acc = fmaf(g_A[2][v * 128 + o], dvec[o] * __ldg(W_r + o), acc);
        g_c[v] = acc * c_ISV;
    }
}

// ---------------------------------------------------------------------------
// out[n,m] = time_n * sum_v x_v[n,v,m] * c[v]. FOUR nodes per warp (12
// independent LDG.128/thread in flight); lane l owns channels 4l..4l+3.
// ---------------------------------------------------------------------------
__global__ void k_out(const float* __restrict__ feat,
                      const float* __restrict__ times,
                      float* __restrict__ out) {
    const int gw = (blockIdx.x * blockDim.x + threadIdx.x) >> 5;
    const int lane = threadIdx.x & 31;
    const int n0 = 4 * gw;
    if (n0 >= NN) return;

    const float4 cv = *(const float4*)(g_c + 4 * lane);
    float r[4][3];
#pragma unroll
    for (int q = 0; q < 4; q++) {
        const float* b = feat + (size_t)(n0 + q) * 512 + 128 + 12 * lane;
        const float4 x0 = *(const float4*)(b);
        const float4 x1 = *(const float4*)(b + 4);
        const float4 x2 = *(const float4*)(b + 8);
        r[q][0] = x0.x * cv.x + x0.w * cv.y + x1.z * cv.z + x2.y * cv.w;
        r[q][1] = x0.y * cv.x + x1.x * cv.y + x1.w * cv.z + x2.z * cv.w;
        r[q][2] = x0.z * cv.x + x1.y * cv.y + x2.x * cv.z + x2.w * cv.w;
    }
#pragma unroll
    for (int off = 16; off > 0; off >>= 1) {
#pragma unroll
        for (int q = 0; q < 4; q++) {
            r[q][0] += __shfl_xor_sync(0xffffffffu, r[q][0], off);
            r[q][1] += __shfl_xor_sync(0xffffffffu, r[q][1], off);
            r[q][2] += __shfl_xor_sync(0xffffffffu, r[q][2], off);
        }
    }
    if (lane < 4) {
        const int n = n0 + lane;
        const float tm = times[n];
        out[n * 3 + 0] = tm * r[lane][0];
        out[n * 3 + 1] = tm * r[lane][1];
        out[n * 3 + 2] = tm * r[lane][2];
    }
}

// ---------------------------------------------------------------------------
extern "C" void kernel_launch(void* const* d_in, const int* in_sizes, int n_in,
                              void* d_out, int out_size) {
    const float* feat    = (const float*)d_in[0];
    const float* times   = (const float*)d_in[1];
    const float* W_time  = (const float*)d_in[2];
    const float* W_tp1   = (const float*)d_in[4];
    const float* Wv      = (const float*)d_in[6];
    const float* gamma_v = (const float*)d_in[9];
    const float* W_r     = (const float*)d_in[10];
    float* out = (float*)d_out;

    k_gram<<<NPART, 256>>>(feat, times);
    k_greduce<<<67, 256>>>(Wv);
    k_chain<<<8, 256>>>(W_time, W_tp1, gamma_v, W_r);
    k_out<<<(NN / 4 * 32) / 256, 256>>>(feat, times, out);
}